// round 3
// baseline (speedup 1.0000x reference)
#include <cuda_runtime.h>
#include <cuda_fp16.h>
#include <math.h>

#define NB 256
#define NJ 10
#define NI 1152
#define NP 16
#define NQ 8
#define NCH 9          // i-chunks
#define CH 128         // i per chunk
#define JP (NJ * NP)   // 160

// Scratch (device globals — no allocation in kernel_launch).
__device__ __half g_hat[(size_t)NB * NJ * NI * NP];   // [b][j][i][p], 94.4 MB
__device__ float  g_s0f[NB * JP];                     // fused s0 accumulator

// ---------------------------------------------------------------------------
// K1: hat[b,j,i,p] = sum_q W[j,i,p,q] * in[b,i,q]  (fp16 store)
// Fused: accumulate s0[b,j,p] = sum_i hat via warp butterfly + global REDG.
// grid (ic=18, j=10, bc=4), block 256. Thread owns (i, p-quad).
// ---------------------------------------------------------------------------
__global__ __launch_bounds__(256) void k_hat(const float* __restrict__ in,
                                             const float* __restrict__ W) {
    const int ic = blockIdx.x;          // 0..17  (64 i each)
    const int j  = blockIdx.y;          // 0..9
    const int bc = blockIdx.z;          // 0..3   (64 b each)
    const int t  = threadIdx.x;
    const int p4 = t & 3;               // which p-quad
    const int il = t >> 2;              // 0..63
    const int i  = ic * 64 + il;
    const int lane = t & 31;

    // Load this thread's 4x8 W slice once (contiguous 128 B).
    float w[4][8];
    {
        const float4* Wv = (const float4*)(W + ((size_t)(j * NI + i) * NP + p4 * 4) * NQ);
        #pragma unroll
        for (int pp = 0; pp < 4; pp++) {
            float4 a = Wv[pp * 2], c = Wv[pp * 2 + 1];
            w[pp][0] = a.x; w[pp][1] = a.y; w[pp][2] = a.z; w[pp][3] = a.w;
            w[pp][4] = c.x; w[pp][5] = c.y; w[pp][6] = c.z; w[pp][7] = c.w;
        }
    }

    __shared__ float in_s[8 * 64 * NQ];   // 16 KB

    for (int g = 0; g < 8; g++) {
        const int b0 = bc * 64 + g * 8;
        __syncthreads();
        #pragma unroll
        for (int k = 0; k < 4; k++) {
            int m   = t + 256 * k;        // float4 index 0..1023
            int bo  = m >> 7;             // 128 float4 per b
            int pos = m & 127;
            ((float4*)in_s)[m] =
                ((const float4*)(in + ((size_t)(b0 + bo) * NI + ic * 64) * NQ))[pos];
        }
        __syncthreads();
        #pragma unroll
        for (int bb = 0; bb < 8; bb++) {
            const int b = b0 + bb;
            const float* xs = in_s + (bb * 64 + il) * NQ;
            float x0 = xs[0], x1 = xs[1], x2 = xs[2], x3 = xs[3];
            float x4 = xs[4], x5 = xs[5], x6 = xs[6], x7 = xs[7];
            float r[4];
            #pragma unroll
            for (int pp = 0; pp < 4; pp++) {
                r[pp] = w[pp][0] * x0 + w[pp][1] * x1 + w[pp][2] * x2 + w[pp][3] * x3
                      + w[pp][4] * x4 + w[pp][5] * x5 + w[pp][6] * x6 + w[pp][7] * x7;
            }
            // fp16 store (8 bytes)
            union { __half2 h2[2]; uint2 u; } pk;
            pk.h2[0] = __floats2half2_rn(r[0], r[1]);
            pk.h2[1] = __floats2half2_rn(r[2], r[3]);
            *(uint2*)(g_hat + ((size_t)(b * NJ + j) * NI + i) * NP + p4 * 4) = pk.u;

            // fused s0: butterfly over il-bits within warp
            #pragma unroll
            for (int pp = 0; pp < 4; pp++) {
                r[pp] += __shfl_xor_sync(0xffffffffu, r[pp], 4);
                r[pp] += __shfl_xor_sync(0xffffffffu, r[pp], 8);
                r[pp] += __shfl_xor_sync(0xffffffffu, r[pp], 16);
            }
            if (lane < 4) {
                float* dst = g_s0f + (b * NJ + j) * NP + p4 * 4;
                #pragma unroll
                for (int pp = 0; pp < 4; pp++) atomicAdd(dst + pp, r[pp]);
            }
        }
    }
}

// ---------------------------------------------------------------------------
// K2 (mega): per-b block does s0-squash, route pass B, mid-squash,
// route pass C, final squash -> d_out. grid 256 (b), block 256.
// ---------------------------------------------------------------------------
__global__ __launch_bounds__(256) void k_mega(float* __restrict__ out) {
    const int b = blockIdx.x;
    const int t = threadIdx.x;

    __shared__ float cbuf[NJ * CH];   // logits -> c, 5 KB
    __shared__ float ov[JP];          // current routing vector

    // --- out0 = squash(0.1 * s0) ---
    float out0_t = 0.f;
    if (t < JP) {
        float s = g_s0f[b * JP + t] * 0.1f;   // c0 = 1/J exactly
        float sq = s * s;
        sq += __shfl_xor_sync(0xffffffffu, sq, 1);
        sq += __shfl_xor_sync(0xffffffffu, sq, 2);
        sq += __shfl_xor_sync(0xffffffffu, sq, 4);
        sq += __shfl_xor_sync(0xffffffffu, sq, 8);
        float sc = sq / ((1.f + sq) * sqrtf(sq + 1e-7f));
        out0_t = s * sc;
        ov[t] = out0_t;
    }
    __syncthreads();

    const __half* hb = g_hat + (size_t)b * NJ * NI * NP;

    #pragma unroll 1
    for (int pass = 0; pass < 2; pass++) {
        float acc0 = 0.f, acc1 = 0.f, acc2 = 0.f, acc3 = 0.f;

        #pragma unroll 1
        for (int ic = 0; ic < NCH; ic++) {
            const int i0 = ic * CH;

            // Phase 1: logits[j][il] = dot16(hat[b,j,i0+il,:], ov[j,:])
            #pragma unroll
            for (int k = 0; k < 5; k++) {
                int idx = t + 256 * k;          // 0..1279
                int j = idx >> 7, il = idx & 127;
                const __half* h = hb + (size_t)(j * NI + i0 + il) * NP;
                union { uint4 u; __half2 h2[4]; } a, c;
                a.u = ((const uint4*)h)[0];
                c.u = ((const uint4*)h)[1];
                const float* av = ov + j * NP;
                float d = 0.f;
                #pragma unroll
                for (int k2 = 0; k2 < 4; k2++) {
                    float2 f = __half22float2(a.h2[k2]);
                    d = fmaf(f.x, av[2 * k2], d);
                    d = fmaf(f.y, av[2 * k2 + 1], d);
                }
                #pragma unroll
                for (int k2 = 0; k2 < 4; k2++) {
                    float2 f = __half22float2(c.h2[k2]);
                    d = fmaf(f.x, av[8 + 2 * k2], d);
                    d = fmaf(f.y, av[8 + 2 * k2 + 1], d);
                }
                cbuf[idx] = d;
            }
            __syncthreads();

            // Phase 2: softmax over j per i (thread-per-i, registers)
            if (t < CH) {
                float v[NJ];
                float mx = -1e30f;
                #pragma unroll
                for (int j = 0; j < NJ; j++) { v[j] = cbuf[j * CH + t]; mx = fmaxf(mx, v[j]); }
                float sum = 0.f;
                #pragma unroll
                for (int j = 0; j < NJ; j++) { v[j] = __expf(v[j] - mx); sum += v[j]; }
                float inv = 1.f / sum;
                #pragma unroll
                for (int j = 0; j < NJ; j++) cbuf[j * CH + t] = v[j] * inv;
            }
            __syncthreads();

            // Phase 3: acc[j,p] += sum_il c[j,il] * hat[..]  (L1-resident, 4-way ILP)
            if (t < JP) {
                const int j = t >> 4, p = t & 15;
                const __half* hc = hb + (size_t)(j * NI + i0) * NP + p;
                const float* cc = cbuf + j * CH;
                #pragma unroll
                for (int il = 0; il < CH; il += 4) {
                    acc0 = fmaf(__half2float(hc[(size_t)(il + 0) * NP]), cc[il + 0], acc0);
                    acc1 = fmaf(__half2float(hc[(size_t)(il + 1) * NP]), cc[il + 1], acc1);
                    acc2 = fmaf(__half2float(hc[(size_t)(il + 2) * NP]), cc[il + 2], acc2);
                    acc3 = fmaf(__half2float(hc[(size_t)(il + 3) * NP]), cc[il + 3], acc3);
                }
            }
            __syncthreads();   // cbuf reused next chunk
        }

        // squash(acc) for this pass
        if (t < JP) {
            float s = (acc0 + acc1) + (acc2 + acc3);
            float sq = s * s;
            sq += __shfl_xor_sync(0xffffffffu, sq, 1);
            sq += __shfl_xor_sync(0xffffffffu, sq, 2);
            sq += __shfl_xor_sync(0xffffffffu, sq, 4);
            sq += __shfl_xor_sync(0xffffffffu, sq, 8);
            float sc = sq / ((1.f + sq) * sqrtf(sq + 1e-7f));
            float o = s * sc;
            if (pass == 0) ov[t] = out0_t + o;       // routing vec for pass C
            else           out[b * JP + t] = o;       // final output
        }
        __syncthreads();
    }
}

extern "C" void kernel_launch(void* const* d_in, const int* in_sizes, int n_in,
                              void* d_out, int out_size) {
    const float* in = (const float*)d_in[0];   // [256,1152,8]
    const float* W  = (const float*)d_in[1];   // [10,1152,16,8]
    float* out = (float*)d_out;                // [256,10,16]

    void* s0p = nullptr;
    cudaGetSymbolAddress(&s0p, g_s0f);
    cudaMemsetAsync(s0p, 0, sizeof(float) * NB * JP);

    k_hat<<<dim3(18, 10, 4), 256>>>(in, W);
    k_mega<<<NB, 256>>>(out);
}

// round 4
// speedup vs baseline: 1.1421x; 1.1421x over previous
#include <cuda_runtime.h>
#include <cuda_fp16.h>
#include <math.h>

#define NB 256
#define NJ 10
#define NI 1152
#define NP 16
#define NQ 8
#define NCH 9           // i-chunks
#define CH 128          // i per chunk
#define JP (NJ * NP)    // 160
#define CBS 136         // cbuf stride (pad: 136%32=8 -> j rows hit disjoint banks)
#define JST 1032        // words per j-block in smem hat (1024 + 8 pad)

// Scratch (device globals — no allocation in kernel_launch).
__device__ __half g_hat[(size_t)NB * NJ * NI * NP];   // [b][j][i][p], 94.4 MB
__device__ float  g_s0f[NB * JP];                     // fused s0 accumulator
__device__ float  g_spartB[NB * NCH * JP];            // pass-B partials
__device__ float  g_spartC[NB * NCH * JP];            // pass-C partials

// ---------------------------------------------------------------------------
// K1: hat[b,j,i,p] = sum_q W[j,i,p,q] * in[b,i,q]  (fp16 store)
// Fused s0 accumulation: warp butterfly -> SMEM atomics -> 1 coalesced global
// flush per 8-batch group (8x fewer global REDs than per-warp flush).
// grid (ic=18, j=10, bc=4), block 256. Thread owns (i, p-quad).
// ---------------------------------------------------------------------------
__global__ __launch_bounds__(256) void k_hat(const float* __restrict__ in,
                                             const float* __restrict__ W) {
    const int ic = blockIdx.x;          // 0..17  (64 i each)
    const int j  = blockIdx.y;          // 0..9
    const int bc = blockIdx.z;          // 0..3   (64 b each)
    const int t  = threadIdx.x;
    const int p4 = t & 3;               // which p-quad
    const int il = t >> 2;              // 0..63
    const int i  = ic * 64 + il;
    const int lane = t & 31;

    // Load this thread's 4x8 W slice once (contiguous 128 B).
    float w[4][8];
    {
        const float4* Wv = (const float4*)(W + ((size_t)(j * NI + i) * NP + p4 * 4) * NQ);
        #pragma unroll
        for (int pp = 0; pp < 4; pp++) {
            float4 a = Wv[pp * 2], c = Wv[pp * 2 + 1];
            w[pp][0] = a.x; w[pp][1] = a.y; w[pp][2] = a.z; w[pp][3] = a.w;
            w[pp][4] = c.x; w[pp][5] = c.y; w[pp][6] = c.z; w[pp][7] = c.w;
        }
    }

    __shared__ float in_s[8 * 64 * NQ];   // 16 KB
    __shared__ float s0s[8 * 16];         // [bb][p] per g-group

    if (t < 128) s0s[t] = 0.f;

    for (int g = 0; g < 8; g++) {
        const int b0 = bc * 64 + g * 8;
        __syncthreads();                  // in_s reuse + s0s zero visible
        #pragma unroll
        for (int k = 0; k < 4; k++) {
            int m   = t + 256 * k;        // float4 index 0..1023
            int bo  = m >> 7;             // 128 float4 per b
            int pos = m & 127;
            ((float4*)in_s)[m] =
                ((const float4*)(in + ((size_t)(b0 + bo) * NI + ic * 64) * NQ))[pos];
        }
        __syncthreads();
        #pragma unroll
        for (int bb = 0; bb < 8; bb++) {
            const int b = b0 + bb;
            const float* xs = in_s + (bb * 64 + il) * NQ;
            float x0 = xs[0], x1 = xs[1], x2 = xs[2], x3 = xs[3];
            float x4 = xs[4], x5 = xs[5], x6 = xs[6], x7 = xs[7];
            float r[4];
            #pragma unroll
            for (int pp = 0; pp < 4; pp++) {
                r[pp] = w[pp][0] * x0 + w[pp][1] * x1 + w[pp][2] * x2 + w[pp][3] * x3
                      + w[pp][4] * x4 + w[pp][5] * x5 + w[pp][6] * x6 + w[pp][7] * x7;
            }
            // fp16 store (8 bytes, coalesced 256 B per warp)
            union { __half2 h2[2]; uint2 u; } pk;
            pk.h2[0] = __floats2half2_rn(r[0], r[1]);
            pk.h2[1] = __floats2half2_rn(r[2], r[3]);
            *(uint2*)(g_hat + ((size_t)(b * NJ + j) * NI + i) * NP + p4 * 4) = pk.u;

            // s0: butterfly over il-bits within warp, then SMEM atomic
            #pragma unroll
            for (int pp = 0; pp < 4; pp++) {
                r[pp] += __shfl_xor_sync(0xffffffffu, r[pp], 4);
                r[pp] += __shfl_xor_sync(0xffffffffu, r[pp], 8);
                r[pp] += __shfl_xor_sync(0xffffffffu, r[pp], 16);
            }
            if (lane < 4) {
                #pragma unroll
                for (int pp = 0; pp < 4; pp++)
                    atomicAdd(&s0s[bb * 16 + p4 * 4 + pp], r[pp]);
            }
        }
        __syncthreads();
        if (t < 128) {                    // one coalesced flush per g-group
            int bb = t >> 4, p = t & 15;
            atomicAdd(g_s0f + ((b0 + bb) * NJ + j) * NP + p, s0s[t]);
            s0s[t] = 0.f;
        }
    }
}

// ---------------------------------------------------------------------------
// K2/K3: one routing pass. Head recomputes the routing vector (deterministic
// per-b redundant work). Phase 1 loads hat chunk from global, stages it in
// SMEM (bank-padded), dots -> logits. Phase 2 softmax. Phase 3 weighted
// column sum from SMEM (conflict-free). grid (ic=9, b=256), block 256.
// ---------------------------------------------------------------------------
__global__ __launch_bounds__(256) void k_route(const float* __restrict__ spart_in,
                                               float* __restrict__ spart_out,
                                               int pass) {
    const int ic = blockIdx.x;
    const int b  = blockIdx.y;
    const int t  = threadIdx.x;

    __shared__ __align__(16) unsigned int smh[NJ * JST];  // hat chunk, 41.3 KB
    __shared__ float cbuf[NJ * CBS];                      // logits -> c, 5.4 KB
    __shared__ float ov[JP];                              // routing vector

    // --- head: routing vector = out0 (+ squash(s_prev) for pass C) ---
    if (t < JP) {
        float s = g_s0f[b * JP + t] * 0.1f;   // c0 = 1/J exactly
        float sq = s * s;
        sq += __shfl_xor_sync(0xffffffffu, sq, 1);
        sq += __shfl_xor_sync(0xffffffffu, sq, 2);
        sq += __shfl_xor_sync(0xffffffffu, sq, 4);
        sq += __shfl_xor_sync(0xffffffffu, sq, 8);
        float sc = sq / ((1.f + sq) * sqrtf(sq + 1e-7f));
        float v = s * sc;                      // out0
        if (pass) {
            float s1 = 0.f;
            #pragma unroll
            for (int c2 = 0; c2 < NCH; c2++)
                s1 += spart_in[(b * NCH + c2) * JP + t];
            float q = s1 * s1;
            q += __shfl_xor_sync(0xffffffffu, q, 1);
            q += __shfl_xor_sync(0xffffffffu, q, 2);
            q += __shfl_xor_sync(0xffffffffu, q, 4);
            q += __shfl_xor_sync(0xffffffffu, q, 8);
            float sc1 = q / ((1.f + q) * sqrtf(q + 1e-7f));
            v += s1 * sc1;                     // out0 + out1
        }
        ov[t] = v;
    }
    __syncthreads();

    const __half* hb = g_hat + (size_t)b * NJ * NI * NP;
    const int i0 = ic * CH;

    // Phase 1: load + stage + logits[j][il] = dot16(hat_row, ov[j,:])
    #pragma unroll
    for (int k = 0; k < 5; k++) {
        int idx = t + 256 * k;          // 0..1279
        int j = idx >> 7, il = idx & 127;
        const __half* h = hb + (size_t)(j * NI + i0 + il) * NP;
        union { uint4 u; __half2 h2[4]; } a, c;
        a.u = ((const uint4*)h)[0];
        c.u = ((const uint4*)h)[1];
        const float* av = ov + j * NP;
        float d = 0.f;
        #pragma unroll
        for (int k2 = 0; k2 < 4; k2++) {
            float2 f = __half22float2(a.h2[k2]);
            d = fmaf(f.x, av[2 * k2], d);
            d = fmaf(f.y, av[2 * k2 + 1], d);
        }
        #pragma unroll
        for (int k2 = 0; k2 < 4; k2++) {
            float2 f = __half22float2(c.h2[k2]);
            d = fmaf(f.x, av[8 + 2 * k2], d);
            d = fmaf(f.y, av[8 + 2 * k2 + 1], d);
        }
        cbuf[j * CBS + il] = d;
        uint4* dst = (uint4*)(smh + j * JST + il * 8);
        dst[0] = a.u;
        dst[1] = c.u;
    }
    __syncthreads();

    // Phase 2: softmax over j per i (thread-per-i, registers)
    if (t < CH) {
        float v[NJ];
        float mx = -1e30f;
        #pragma unroll
        for (int j = 0; j < NJ; j++) { v[j] = cbuf[j * CBS + t]; mx = fmaxf(mx, v[j]); }
        float sum = 0.f;
        #pragma unroll
        for (int j = 0; j < NJ; j++) { v[j] = __expf(v[j] - mx); sum += v[j]; }
        float inv = 1.f / sum;
        #pragma unroll
        for (int j = 0; j < NJ; j++) cbuf[j * CBS + t] = v[j] * inv;
    }
    __syncthreads();

    // Phase 3: s_partial[j,p] = sum_il c[j,il] * hat  (SMEM, conflict-free)
    if (t < JP) {
        const int j = t >> 4, p = t & 15;
        const __half* hrow = (const __half*)(smh + j * JST) + p;   // stride 16 halves
        const float* cc = cbuf + j * CBS;
        float a0 = 0.f, a1 = 0.f, a2 = 0.f, a3 = 0.f;
        #pragma unroll
        for (int il = 0; il < CH; il += 4) {
            a0 = fmaf(__half2float(hrow[(il + 0) * 16]), cc[il + 0], a0);
            a1 = fmaf(__half2float(hrow[(il + 1) * 16]), cc[il + 1], a1);
            a2 = fmaf(__half2float(hrow[(il + 2) * 16]), cc[il + 2], a2);
            a3 = fmaf(__half2float(hrow[(il + 3) * 16]), cc[il + 3], a3);
        }
        spart_out[(b * NCH + ic) * JP + t] = (a0 + a1) + (a2 + a3);
    }
}

// ---------------------------------------------------------------------------
// K4: final = squash(sum of pass-C partials) -> d_out. grid 256 (b), block 160.
// ---------------------------------------------------------------------------
__global__ __launch_bounds__(160) void k_final(float* __restrict__ out) {
    const int b = blockIdx.x, t = threadIdx.x;
    float acc = 0.f;
    #pragma unroll
    for (int c2 = 0; c2 < NCH; c2++) acc += g_spartC[(b * NCH + c2) * JP + t];
    float sq = acc * acc;
    sq += __shfl_xor_sync(0xffffffffu, sq, 1);
    sq += __shfl_xor_sync(0xffffffffu, sq, 2);
    sq += __shfl_xor_sync(0xffffffffu, sq, 4);
    sq += __shfl_xor_sync(0xffffffffu, sq, 8);
    float sc = sq / ((1.f + sq) * sqrtf(sq + 1e-7f));
    out[b * JP + t] = acc * sc;
}

extern "C" void kernel_launch(void* const* d_in, const int* in_sizes, int n_in,
                              void* d_out, int out_size) {
    const float* in = (const float*)d_in[0];   // [256,1152,8]
    const float* W  = (const float*)d_in[1];   // [10,1152,16,8]
    float* out = (float*)d_out;                // [256,10,16]

    void* s0p = nullptr;
    cudaGetSymbolAddress(&s0p, g_s0f);
    void* pB = nullptr;
    cudaGetSymbolAddress(&pB, g_spartB);
    void* pC = nullptr;
    cudaGetSymbolAddress(&pC, g_spartC);

    cudaMemsetAsync(s0p, 0, sizeof(float) * NB * JP);

    k_hat<<<dim3(18, 10, 4), 256>>>(in, W);
    k_route<<<dim3(NCH, NB), 256>>>((const float*)pB, (float*)pB, 0);  // pass B
    k_route<<<dim3(NCH, NB), 256>>>((const float*)pB, (float*)pC, 1);  // pass C
    k_final<<<NB, 160>>>(out);
}

// round 5
// speedup vs baseline: 1.6278x; 1.4253x over previous
#include <cuda_runtime.h>
#include <cuda_fp16.h>
#include <math.h>

#define NB 256
#define NJ 10
#define NI 1152
#define NP 16
#define NQ 8
#define NICH 18         // i-chunks for k_hat (64 i each)
#define NCH 9           // i-chunks for route
#define CH 128          // i per route chunk
#define JP (NJ * NP)    // 160
#define CBS 136         // cbuf stride (bank-pad)
#define JST 1032        // uint words per j-block in smem hat (1024 + 8 pad)

// Scratch (device globals — no allocation anywhere).
__device__ __half g_hat[(size_t)NB * NJ * NI * NP];     // [b][j][i][p], 94.4 MB
__device__ float  g_s0part[NICH * NB * JP];             // [ic][b][j*16+p], 2.95 MB
__device__ float  g_spartB[NB * NCH * JP];              // pass-B partials
__device__ float  g_spartC[NB * NCH * JP];              // pass-C partials

// ---------------------------------------------------------------------------
// K1: hat[b,j,i,p] = sum_q W[j,i,p,q]*in[b,i,q], computed in half2 (HFMA2),
// stored fp16. s0 partials via half2 butterfly -> SMEM slots -> deterministic
// per-ic global slots (no atomics, no memset).
// grid (ic=18, j=10, bc=4), block 256. Thread owns (i, p-quad).
// ---------------------------------------------------------------------------
__global__ __launch_bounds__(256) void k_hat(const float* __restrict__ in,
                                             const float* __restrict__ W) {
    const int ic = blockIdx.x;          // 0..17  (64 i each)
    const int j  = blockIdx.y;          // 0..9
    const int bc = blockIdx.z;          // 0..3   (64 b each)
    const int t  = threadIdx.x;
    const int p4 = t & 3;               // p-quad
    const int il = t >> 2;              // 0..63
    const int i  = ic * 64 + il;
    const int lane = t & 31;
    const int wrp  = t >> 5;

    // Load W slice (4 p rows x 8 q, fp32) and pack: w01[q]=(W[p0][q],W[p1][q]).
    __half2 w01[8], w23[8];
    {
        float w[4][8];
        const float4* Wv = (const float4*)(W + ((size_t)(j * NI + i) * NP + p4 * 4) * NQ);
        #pragma unroll
        for (int pp = 0; pp < 4; pp++) {
            float4 a = Wv[pp * 2], c = Wv[pp * 2 + 1];
            w[pp][0] = a.x; w[pp][1] = a.y; w[pp][2] = a.z; w[pp][3] = a.w;
            w[pp][4] = c.x; w[pp][5] = c.y; w[pp][6] = c.z; w[pp][7] = c.w;
        }
        #pragma unroll
        for (int q = 0; q < 8; q++) {
            w01[q] = __floats2half2_rn(w[0][q], w[1][q]);
            w23[q] = __floats2half2_rn(w[2][q], w[3][q]);
        }
    }

    __shared__ __half2 in_s[8 * 64 * NQ];   // duplicated half2 inputs, 16 KB
    __shared__ float   s0w[8 * 128];        // [warp][bb*16+p], 4 KB

    for (int g = 0; g < 8; g++) {
        const int b0 = bc * 64 + g * 8;
        __syncthreads();                     // in_s reuse safe
        #pragma unroll
        for (int k = 0; k < 4; k++) {
            int m   = t + 256 * k;           // float4 index 0..1023
            int bo  = m >> 7;                // 128 float4 per b
            int pos = m & 127;
            float4 v = ((const float4*)(in + ((size_t)(b0 + bo) * NI + ic * 64) * NQ))[pos];
            __half2* dst = in_s + (size_t)bo * 512 + pos * 4;   // 512 half2 per b
            dst[0] = __floats2half2_rn(v.x, v.x);
            dst[1] = __floats2half2_rn(v.y, v.y);
            dst[2] = __floats2half2_rn(v.z, v.z);
            dst[3] = __floats2half2_rn(v.w, v.w);
        }
        __syncthreads();
        #pragma unroll
        for (int bb = 0; bb < 8; bb++) {
            const int b = b0 + bb;
            const __half2* xs = in_s + (bb * 64 + il) * NQ;
            __half2 x0 = xs[0], x1 = xs[1], x2 = xs[2], x3 = xs[3];
            __half2 x4 = xs[4], x5 = xs[5], x6 = xs[6], x7 = xs[7];

            // (r0,r1) and (r2,r3): two independent 4-chains + combine
            __half2 c0 = __hmul2(x0, w01[0]);
            c0 = __hfma2(x1, w01[1], c0);
            c0 = __hfma2(x2, w01[2], c0);
            c0 = __hfma2(x3, w01[3], c0);
            __half2 c1 = __hmul2(x4, w01[4]);
            c1 = __hfma2(x5, w01[5], c1);
            c1 = __hfma2(x6, w01[6], c1);
            c1 = __hfma2(x7, w01[7], c1);
            __half2 r01 = __hadd2(c0, c1);

            __half2 d0 = __hmul2(x0, w23[0]);
            d0 = __hfma2(x1, w23[1], d0);
            d0 = __hfma2(x2, w23[2], d0);
            d0 = __hfma2(x3, w23[3], d0);
            __half2 d1 = __hmul2(x4, w23[4]);
            d1 = __hfma2(x5, w23[5], d1);
            d1 = __hfma2(x6, w23[6], d1);
            d1 = __hfma2(x7, w23[7], d1);
            __half2 r23 = __hadd2(d0, d1);

            // store hat (8 B, already fp16-packed)
            union { __half2 h2[2]; uint2 u; } pk;
            pk.h2[0] = r01; pk.h2[1] = r23;
            *(uint2*)(g_hat + ((size_t)(b * NJ + j) * NI + i) * NP + p4 * 4) = pk.u;

            // s0 butterfly over il-octet in half2 (6 shfls)
            union { __half2 h; unsigned int u; } s01, s23;
            s01.h = r01; s23.h = r23;
            #pragma unroll
            for (int d2 = 4; d2 <= 16; d2 <<= 1) {
                union { __half2 h; unsigned int u; } o1, o2;
                o1.u = __shfl_xor_sync(0xffffffffu, s01.u, d2);
                o2.u = __shfl_xor_sync(0xffffffffu, s23.u, d2);
                s01.h = __hadd2(s01.h, o1.h);
                s23.h = __hadd2(s23.h, o2.h);
            }
            if (lane < 4) {                  // lane == p4 here
                float2 f01 = __half22float2(s01.h);
                float2 f23 = __half22float2(s23.h);
                float4 v; v.x = f01.x; v.y = f01.y; v.z = f23.x; v.w = f23.y;
                *(float4*)(s0w + wrp * 128 + bb * 16 + lane * 4) = v;
            }
        }
        __syncthreads();                     // s0w complete
        if (t < 128) {                       // deterministic flush, no atomics
            int bb2 = t >> 4, p = t & 15;
            float a = 0.f;
            #pragma unroll
            for (int w8 = 0; w8 < 8; w8++) a += s0w[w8 * 128 + t];
            g_s0part[(ic * NB + b0 + bb2) * JP + j * NP + p] = a;
        }
    }
}

// ---------------------------------------------------------------------------
// K2/K3: one routing pass. Head: sum s0 slots -> out0 (+squash(s_prev) for
// pass C), pack ov to half2. Phase 1: load hat chunk (half2 dot -> logits),
// stage in SMEM. Phase 2: softmax. Phase 3: weighted column sum from SMEM.
// grid (ic=9, b=256), block 256.
// ---------------------------------------------------------------------------
__global__ __launch_bounds__(256) void k_route(const float* __restrict__ spart_in,
                                               float* __restrict__ spart_out,
                                               int pass) {
    const int ic = blockIdx.x;
    const int b  = blockIdx.y;
    const int t  = threadIdx.x;

    __shared__ __align__(16) unsigned int smh[NJ * JST];  // hat chunk, 41.3 KB
    __shared__ float   cbuf[NJ * CBS];                    // logits -> c
    __shared__ float   ov[JP];                            // routing vector f32
    __shared__ __half2 ovh[JP / 2];                       // packed half2

    if (t < JP) {
        float s = 0.f;
        #pragma unroll
        for (int c2 = 0; c2 < NICH; c2++) s += g_s0part[(c2 * NB + b) * JP + t];
        s *= 0.1f;                             // c0 = 1/J exactly
        float sq = s * s;
        sq += __shfl_xor_sync(0xffffffffu, sq, 1);
        sq += __shfl_xor_sync(0xffffffffu, sq, 2);
        sq += __shfl_xor_sync(0xffffffffu, sq, 4);
        sq += __shfl_xor_sync(0xffffffffu, sq, 8);
        float sc = sq / ((1.f + sq) * sqrtf(sq + 1e-7f));
        float v = s * sc;                      // out0
        if (pass) {
            float s1 = 0.f;
            #pragma unroll
            for (int c2 = 0; c2 < NCH; c2++)
                s1 += spart_in[(b * NCH + c2) * JP + t];
            float q = s1 * s1;
            q += __shfl_xor_sync(0xffffffffu, q, 1);
            q += __shfl_xor_sync(0xffffffffu, q, 2);
            q += __shfl_xor_sync(0xffffffffu, q, 4);
            q += __shfl_xor_sync(0xffffffffu, q, 8);
            float sc1 = q / ((1.f + q) * sqrtf(q + 1e-7f));
            v += s1 * sc1;                     // out0 + out1
        }
        ov[t] = v;
    }
    __syncthreads();
    if (t < JP / 2) ovh[t] = __floats2half2_rn(ov[2 * t], ov[2 * t + 1]);
    __syncthreads();

    const __half* hb = g_hat + (size_t)b * NJ * NI * NP;
    const int i0 = ic * CH;

    // Phase 1: load + stage + logits (half2 dot)
    #pragma unroll
    for (int k = 0; k < 5; k++) {
        int idx = t + 256 * k;          // 0..1279
        int j = idx >> 7, il = idx & 127;
        const __half* h = hb + (size_t)(j * NI + i0 + il) * NP;
        union { uint4 u; __half2 h2[4]; } a, c;
        a.u = ((const uint4*)h)[0];
        c.u = ((const uint4*)h)[1];
        const __half2* av = ovh + j * 8;
        __half2 acc0 = __hmul2(a.h2[0], av[0]);
        acc0 = __hfma2(a.h2[1], av[1], acc0);
        acc0 = __hfma2(a.h2[2], av[2], acc0);
        acc0 = __hfma2(a.h2[3], av[3], acc0);
        __half2 acc1 = __hmul2(c.h2[0], av[4]);
        acc1 = __hfma2(c.h2[1], av[5], acc1);
        acc1 = __hfma2(c.h2[2], av[6], acc1);
        acc1 = __hfma2(c.h2[3], av[7], acc1);
        float2 f = __half22float2(__hadd2(acc0, acc1));
        cbuf[j * CBS + il] = f.x + f.y;
        uint4* dst = (uint4*)(smh + j * JST + il * 8);
        dst[0] = a.u;
        dst[1] = c.u;
    }
    __syncthreads();

    // Phase 2: softmax over j per i
    if (t < CH) {
        float v[NJ];
        float mx = -1e30f;
        #pragma unroll
        for (int j = 0; j < NJ; j++) { v[j] = cbuf[j * CBS + t]; mx = fmaxf(mx, v[j]); }
        float sum = 0.f;
        #pragma unroll
        for (int j = 0; j < NJ; j++) { v[j] = __expf(v[j] - mx); sum += v[j]; }
        float inv = 1.f / sum;
        #pragma unroll
        for (int j = 0; j < NJ; j++) cbuf[j * CBS + t] = v[j] * inv;
    }
    __syncthreads();

    // Phase 3: s_partial[j,p] = sum_il c[j,il] * hat (SMEM, 4-way ILP)
    if (t < JP) {
        const int j = t >> 4, p = t & 15;
        const __half* hrow = (const __half*)(smh + j * JST) + p;
        const float* cc = cbuf + j * CBS;
        float a0 = 0.f, a1 = 0.f, a2 = 0.f, a3 = 0.f;
        #pragma unroll
        for (int il = 0; il < CH; il += 4) {
            a0 = fmaf(__half2float(hrow[(il + 0) * 16]), cc[il + 0], a0);
            a1 = fmaf(__half2float(hrow[(il + 1) * 16]), cc[il + 1], a1);
            a2 = fmaf(__half2float(hrow[(il + 2) * 16]), cc[il + 2], a2);
            a3 = fmaf(__half2float(hrow[(il + 3) * 16]), cc[il + 3], a3);
        }
        spart_out[(b * NCH + ic) * JP + t] = (a0 + a1) + (a2 + a3);
    }
}

// ---------------------------------------------------------------------------
// K4: final = squash(sum of pass-C partials) -> d_out.
// ---------------------------------------------------------------------------
__global__ __launch_bounds__(160) void k_final(float* __restrict__ out) {
    const int b = blockIdx.x, t = threadIdx.x;
    float acc = 0.f;
    #pragma unroll
    for (int c2 = 0; c2 < NCH; c2++) acc += g_spartC[(b * NCH + c2) * JP + t];
    float sq = acc * acc;
    sq += __shfl_xor_sync(0xffffffffu, sq, 1);
    sq += __shfl_xor_sync(0xffffffffu, sq, 2);
    sq += __shfl_xor_sync(0xffffffffu, sq, 4);
    sq += __shfl_xor_sync(0xffffffffu, sq, 8);
    float sc = sq / ((1.f + sq) * sqrtf(sq + 1e-7f));
    out[b * JP + t] = acc * sc;
}

extern "C" void kernel_launch(void* const* d_in, const int* in_sizes, int n_in,
                              void* d_out, int out_size) {
    const float* in = (const float*)d_in[0];   // [256,1152,8]
    const float* W  = (const float*)d_in[1];   // [10,1152,16,8]
    float* out = (float*)d_out;                // [256,10,16]

    void* pB = nullptr; cudaGetSymbolAddress(&pB, g_spartB);
    void* pC = nullptr; cudaGetSymbolAddress(&pC, g_spartC);

    k_hat<<<dim3(NICH, NJ, 4), 256>>>(in, W);
    k_route<<<dim3(NCH, NB), 256>>>((const float*)pB, (float*)pB, 0);  // pass B
    k_route<<<dim3(NCH, NB), 256>>>((const float*)pB, (float*)pC, 1);  // pass C
    k_final<<<NB, 160>>>(out);
}